// round 6
// baseline (speedup 1.0000x reference)
#include <cuda_runtime.h>
#include <cstdint>

#define BN 64
#define PP 8732
#define CC 81
#define KT 16
#define NR (BN * PP)          // 558848
#define TROWS 128
#define CEB 2183              // NR / 256 tiles-pairs
#define NCH 16
#define CHUNK 546
#define MBLK (BN * NCH)       // 1024
#define THRESH 0.5f
#define VAR0 0.1f
#define VAR1 0.2f
#define SEGLEN 2183           // PP / 4
#define TPK 1024
#define PPADK 9216            // 1024 * 9

// ---------------- scratch ----------------
__device__ __align__(16) float g_bto[NR];
__device__ __align__(16) int   g_bti[NR];
__device__ __align__(16) float g_lse[NR];
__device__ __align__(16) float g_lm[NR];
__device__ unsigned long long g_best[BN * KT];   // idempotent atomicMax accumulator
__device__ float g_loss_l[BN];
__device__ float g_spos[BN];
__device__ float g_loss_c[BN];
__device__ int   g_num_pos[BN];
__device__ int   g_done;                          // self-resetting

// ---------------- PTX helpers ----------------
static __device__ __forceinline__ unsigned su32(const void* p) {
    return (unsigned)__cvta_generic_to_shared(p);
}
#define MBAR_INIT(a, c) \
    asm volatile("mbarrier.init.shared.b64 [%0], %1;" :: "r"(a), "r"(c) : "memory")
#define MBAR_EXPECT(a, n) \
    asm volatile("mbarrier.arrive.expect_tx.shared.b64 _, [%0], %1;" :: "r"(a), "r"(n) : "memory")
#define BULK_G2S(dst, src, n, mbar) \
    asm volatile("cp.async.bulk.shared::cta.global.mbarrier::complete_tx::bytes [%0], [%1], %2, [%3];" \
                 :: "r"(dst), "l"(src), "r"(n), "r"(mbar) : "memory")
#define MBAR_WAITP(a, par) do {                                                     \
    unsigned _done = 0;                                                             \
    while (!_done) {                                                                \
        asm volatile("{\n\t.reg .pred p;\n\t"                                       \
            "mbarrier.try_wait.parity.acquire.cta.shared::cta.b64 p, [%1], %2, 0x989680;\n\t" \
            "selp.b32 %0, 1, 0, p;\n\t}"                                            \
            : "=r"(_done) : "r"(a), "r"((unsigned)(par)) : "memory");               \
    }                                                                               \
} while (0)

// ---------------- kernel 1: CE (double-buffered TMA, thread-per-row) + matchA ----------------
extern __shared__ float dynbuf[];    // 2 * TROWS * CC floats for CE role

__global__ __launch_bounds__(128) void k_big(const float* __restrict__ conf,
                                             const float* __restrict__ priors,
                                             const float* __restrict__ targets) {
    const int blk = blockIdx.x;
    const int tid = threadIdx.x;

    if (blk < CEB) {
        // ------- CE role -------
        __shared__ __align__(8) unsigned long long s_mbar[2];
        const unsigned mb0 = su32(&s_mbar[0]);
        const unsigned mb1 = su32(&s_mbar[1]);
        if (tid == 0) { MBAR_INIT(mb0, 1); MBAR_INIT(mb1, 1); }
        __syncthreads();

        const size_t row0 = (size_t)blk * 256;
        const unsigned tb = (unsigned)(TROWS * CC * 4);   // 41472
        if (tid == 0) {
            MBAR_EXPECT(mb0, tb);
            BULK_G2S(su32(dynbuf), conf + row0 * CC, tb, mb0);
            MBAR_EXPECT(mb1, tb);
            BULK_G2S(su32(dynbuf + TROWS * CC), conf + (row0 + TROWS) * CC, tb, mb1);
        }
#pragma unroll
        for (int st = 0; st < 2; st++) {
            MBAR_WAITP(st ? mb1 : mb0, 0);
            const float* row = dynbuf + st * (TROWS * CC) + tid * CC;
            float s0 = 0.0f, s1 = 0.0f, s2 = 0.0f, s3 = 0.0f;
#pragma unroll 10
            for (int i = 0; i + 3 < CC; i += 4) {
                s0 += __expf(row[i]);
                s1 += __expf(row[i + 1]);
                s2 += __expf(row[i + 2]);
                s3 += __expf(row[i + 3]);
            }
            s0 += __expf(row[CC - 1]);
            const float lse = __logf((s0 + s1) + (s2 + s3));
            const size_t gr = row0 + st * TROWS + tid;
            g_lse[gr] = lse;
            g_lm[gr] = lse - row[0];
        }
    } else {
        // ------- matchA role -------
        __shared__ float4 s_pr[CHUNK];
        __shared__ float4 s_tt[KT];
        __shared__ float s_area[KT];
        __shared__ unsigned long long s_best[KT];

        const int q = blk - CEB;
        const int b = q >> 4;
        const int c = q & 15;

        if (tid == 0 && c == 0) {   // per-replay zeroing of accumulators
            g_loss_l[b] = 0.0f;
            g_spos[b] = 0.0f;
            g_num_pos[b] = 0;
        }
        if (tid < KT) {
            const float* tg = targets + (size_t)(b * KT + tid) * 6;
            s_tt[tid] = make_float4(tg[2], tg[3], tg[4], tg[5]);
            s_area[tid] = (tg[4] - tg[2]) * (tg[5] - tg[3]);
            s_best[tid] = 0ull;
        }
        const int p0 = c * CHUNK;
        const int np = (p0 + CHUNK <= PP) ? CHUNK : (PP - p0);
        for (int i = tid; i < np; i += 128)
            s_pr[i] = ((const float4*)priors)[p0 + i];
        __syncthreads();

        // per-prior best truth
        for (int i = tid; i < np; i += 128) {
            const float4 pr = s_pr[i];
            const float parea = (pr.z - pr.x) * (pr.w - pr.y);
            float bestov = -1.0f;
            int besti = 0;
#pragma unroll
            for (int k = 0; k < KT; k++) {
                const float4 t = s_tt[k];
                float ix = fminf(t.z, pr.z) - fmaxf(t.x, pr.x);
                float iy = fminf(t.w, pr.w) - fmaxf(t.y, pr.y);
                float inter = fmaxf(ix, 0.0f) * fmaxf(iy, 0.0f);
                float ov = inter / (s_area[k] + parea - inter);
                if (ov > bestov) { bestov = ov; besti = k; }
            }
            g_bto[b * PP + p0 + i] = bestov;
            g_bti[b * PP + p0 + i] = besti;
        }

        // per-truth best prior: register-local + warp shuffle reduce, 1 atomic/warp/truth
        for (int k = 0; k < KT; k++) {
            const float4 t = s_tt[k];
            const float ta = s_area[k];
            unsigned long long key = 0ull;
            for (int i = tid; i < np; i += 128) {
                const float4 pr = s_pr[i];
                const float parea = (pr.z - pr.x) * (pr.w - pr.y);
                float ix = fminf(t.z, pr.z) - fmaxf(t.x, pr.x);
                float iy = fminf(t.w, pr.w) - fmaxf(t.y, pr.y);
                float inter = fmaxf(ix, 0.0f) * fmaxf(iy, 0.0f);
                float ov = inter / (ta + parea - inter);
                unsigned long long kk =
                    ((unsigned long long)__float_as_uint(ov) << 32) |
                    (unsigned long long)(0xFFFFFFFFu - (unsigned)(p0 + i));
                if (kk > key) key = kk;
            }
#pragma unroll
            for (int o = 16; o; o >>= 1) {
                unsigned long long other = __shfl_xor_sync(0xFFFFFFFFu, key, o);
                if (other > key) key = other;
            }
            if ((tid & 31) == 0)
                atomicMax(&s_best[k], key);
        }
        __syncthreads();
        if (tid < KT)
            atomicMax(&g_best[b * KT + tid], s_best[tid]);
    }
}

// ---------------- kernel 2: conf_t + smooth-L1 + pos-CE + lm patch (4 blocks/image) ----------------
__global__ __launch_bounds__(512) void k_postA(const float* __restrict__ conf,
                                               const float* __restrict__ loc,
                                               const float* __restrict__ priors,
                                               const float* __restrict__ targets) {
    const int b = blockIdx.x >> 2;
    const int seg = blockIdx.x & 3;
    const int tid = threadIdx.x;
    const int bPP = b * PP;

    __shared__ float4 s_tt[KT];
    __shared__ int s_lab[KT];
    __shared__ int s_fp[KT];
    __shared__ float s_fov[KT];
    __shared__ float s_rf[16], s_rs[16];
    __shared__ int s_ri[16];

    if (tid < KT) {
        const float* tg = targets + (size_t)(b * KT + tid) * 6;
        s_lab[tid] = (int)tg[1];
        s_tt[tid] = make_float4(tg[2], tg[3], tg[4], tg[5]);
        unsigned long long key = g_best[b * KT + tid];
        s_fp[tid] = (int)(0xFFFFFFFFu - (unsigned)(key & 0xFFFFFFFFull));
        s_fov[tid] = __uint_as_float((unsigned)(key >> 32));
    }
    __syncthreads();

    const int p0 = seg * SEGLEN;
    const int p1 = p0 + SEGLEN;
    float lsum = 0.0f, spos = 0.0f;
    int cnt = 0;
    for (int p = p0 + tid; p < p1; p += 512) {
        float ov = g_bto[bPP + p];
        int ki = g_bti[bPP + p];
#pragma unroll
        for (int k = 0; k < KT; k++) {     // functional force-assign, last k wins
            if (p == s_fp[k]) { ov = s_fov[k]; ki = k; }
        }
        const int ct = (ov < THRESH) ? 0 : s_lab[ki];
        if (ct > 0) {
            cnt++;
            g_lm[bPP + p] = 0.0f;          // patch loss_mine for positives
            spos += g_lse[bPP + p] - conf[(size_t)(bPP + p) * CC + ct];
            const float4 pr = ((const float4*)priors)[p];
            const float pcx = 0.5f * (pr.x + pr.z), pcy = 0.5f * (pr.y + pr.w);
            const float pw = pr.z - pr.x, ph = pr.w - pr.y;
            const float4 t = s_tt[ki];
            float g0 = (0.5f * (t.x + t.z) - pcx) / (VAR0 * pw);
            float g1 = (0.5f * (t.y + t.w) - pcy) / (VAR0 * ph);
            float g2 = logf((t.z - t.x) / pw) / VAR1;
            float g3 = logf((t.w - t.y) / ph) / VAR1;
            const float4 ld = ((const float4*)loc)[bPP + p];
            float d, ad;
            d = ld.x - g0; ad = fabsf(d); lsum += (ad < 1.0f) ? 0.5f * d * d : ad - 0.5f;
            d = ld.y - g1; ad = fabsf(d); lsum += (ad < 1.0f) ? 0.5f * d * d : ad - 0.5f;
            d = ld.z - g2; ad = fabsf(d); lsum += (ad < 1.0f) ? 0.5f * d * d : ad - 0.5f;
            d = ld.w - g3; ad = fabsf(d); lsum += (ad < 1.0f) ? 0.5f * d * d : ad - 0.5f;
        }
    }
#pragma unroll
    for (int o = 16; o; o >>= 1) {
        lsum += __shfl_xor_sync(0xFFFFFFFFu, lsum, o);
        spos += __shfl_xor_sync(0xFFFFFFFFu, spos, o);
        cnt  += __shfl_xor_sync(0xFFFFFFFFu, cnt, o);
    }
    if ((tid & 31) == 0) {
        const int w = tid >> 5;
        s_rf[w] = lsum; s_rs[w] = spos; s_ri[w] = cnt;
    }
    __syncthreads();
    if (tid == 0) {
        float L = 0.0f, S = 0.0f; int C = 0;
        for (int w = 0; w < 16; w++) { L += s_rf[w]; S += s_rs[w]; C += s_ri[w]; }
        atomicAdd(&g_loss_l[b], L);
        atomicAdd(&g_spos[b], S);
        atomicAdd(&g_num_pos[b], C);
    }
}

// ---------------- kernel 3: per-image radix top-k + fused finalize ----------------
__global__ __launch_bounds__(TPK) void k_topk(float* __restrict__ out) {
    const int b = blockIdx.x;
    const int tid = threadIdx.x;
    const int lane = tid & 31;
    const int w = tid >> 5;

    __shared__ __align__(16) float s_lm[PP];
    __shared__ int s_hist[256];
    __shared__ int s_cum[257];
    __shared__ int s_wtot[8], s_wsuf[8];
    __shared__ unsigned s_prefix;
    __shared__ int s_rem;
    __shared__ float s_rf[32];
    __shared__ int s_ri[32];
    __shared__ int s_last;
    __shared__ __align__(8) unsigned long long s_mbar;

    const unsigned mb = su32(&s_mbar);
    if (tid == 0) {
        MBAR_INIT(mb, 1);
        MBAR_EXPECT(mb, (unsigned)(PP * 4));
        BULK_G2S(su32(s_lm), g_lm + b * PP, (unsigned)(PP * 4), mb);
    }
    if (tid < 256) s_hist[tid] = 0;
    __syncthreads();
    MBAR_WAITP(mb, 0);

    const int npos = g_num_pos[b];
    int k = 3 * npos;
    if (k > PP - 1) k = PP - 1;

    float T = 0.0f;
    if (k > 0) {
        if (tid == 0) { s_prefix = 0u; s_rem = k; }
        __syncthreads();
        for (int shift = 24; shift >= 0; shift -= 8) {
            const unsigned pref = s_prefix;
            const int rem = s_rem;
            const unsigned hm = (shift == 24) ? 0u : (0xFFFFFFFFu << (shift + 8));
            for (int p = tid; p < PPADK; p += TPK) {
                const bool v = p < PP;
                const unsigned bits = v ? __float_as_uint(s_lm[p]) : 0u;
                const int bin = (bits >> shift) & 255;
                const bool pred = v && ((bits & hm) == pref);
                unsigned m = __match_any_sync(0xFFFFFFFFu, bin) &
                             __ballot_sync(0xFFFFFFFFu, pred);
                if (pred && lane == (__ffs(m) - 1))
                    atomicAdd(&s_hist[bin], __popc(m));
            }
            __syncthreads();
            int v = 0;
            if (tid < 256) {                      // warps 0-7: suffix scan within warp
                v = s_hist[tid];
#pragma unroll
                for (int o = 1; o < 32; o <<= 1) {
                    int t2 = __shfl_down_sync(0xFFFFFFFFu, v, o);
                    if (lane + o < 32) v += t2;
                }
                if (lane == 0) s_wtot[w] = v;
            }
            __syncthreads();
            if (tid < 8) {                        // suffix scan over 8 warp totals
                int t2 = s_wtot[tid];
#pragma unroll
                for (int o = 1; o < 8; o <<= 1) {
                    int u = __shfl_down_sync(0xFFu, t2, o);
                    if (tid + o < 8) t2 += u;
                }
                s_wsuf[tid] = t2 - s_wtot[tid];
            }
            __syncthreads();
            if (tid < 256) s_cum[tid] = v + s_wsuf[w];
            if (tid == 0) s_cum[256] = 0;
            __syncthreads();
            if (tid < 256) {
                const int above = s_cum[tid + 1];
                if (s_cum[tid] >= rem && above < rem) {
                    s_prefix = pref | ((unsigned)tid << shift);
                    s_rem = rem - above;
                }
                s_hist[tid] = 0;                  // re-zero for next pass
            }
            __syncthreads();
        }
        const unsigned t = s_prefix;
        float sumgt = 0.0f;
        int cntgt = 0;
        for (int p = tid; p < PP; p += TPK) {
            const float lm = s_lm[p];
            if (__float_as_uint(lm) > t) { sumgt += lm; cntgt++; }
        }
#pragma unroll
        for (int o = 16; o; o >>= 1) {
            sumgt += __shfl_xor_sync(0xFFFFFFFFu, sumgt, o);
            cntgt += __shfl_xor_sync(0xFFFFFFFFu, cntgt, o);
        }
        if (lane == 0) { s_rf[w] = sumgt; s_ri[w] = cntgt; }
        __syncthreads();
        if (tid == 0) {
            float S = 0.0f; int C = 0;
            for (int i = 0; i < 32; i++) { S += s_rf[i]; C += s_ri[i]; }
            T = S + (float)(k - C) * __uint_as_float(t);
        }
    }

    if (tid == 0) {
        g_loss_c[b] = g_spos[b] + T;
        __threadfence();
        s_last = (atomicAdd(&g_done, 1) == BN - 1) ? 1 : 0;
    }
    __syncthreads();
    if (s_last) {
        float lv = 0.0f, cv = 0.0f, nv = 0.0f;
        if (tid < 64) {
            lv = __ldcg(&g_loss_l[tid]);
            cv = __ldcg(&g_loss_c[tid]);
            nv = (float)__ldcg(&g_num_pos[tid]);
#pragma unroll
            for (int o = 16; o; o >>= 1) {
                lv += __shfl_xor_sync(0xFFFFFFFFu, lv, o);
                cv += __shfl_xor_sync(0xFFFFFFFFu, cv, o);
                nv += __shfl_xor_sync(0xFFFFFFFFu, nv, o);
            }
            if (lane == 0) { s_rf[w] = lv; s_rf[w + 2] = cv; s_rf[w + 4] = nv; }
        }
        __syncthreads();
        if (tid == 0) {
            const float L = s_rf[0] + s_rf[1];
            const float Cc = s_rf[2] + s_rf[3];
            const float Nn = s_rf[4] + s_rf[5];
            const float n = fmaxf(Nn, 1.0f);
            out[0] = L / n;
            out[1] = Cc / n;
            g_done = 0;   // self-reset for next replay
        }
    }
}

extern "C" void kernel_launch(void* const* d_in, const int* in_sizes, int n_in,
                              void* d_out, int out_size) {
    const float* loc = (const float*)d_in[0];
    const float* conf = (const float*)d_in[1];
    const float* priors = (const float*)d_in[2];
    const float* targets = (const float*)d_in[3];
    float* out = (float*)d_out;

    const int dynsz = 2 * TROWS * CC * 4;   // 82944 B
    cudaFuncSetAttribute(k_big, cudaFuncAttributeMaxDynamicSharedMemorySize, dynsz);

    k_big<<<CEB + MBLK, 128, dynsz>>>(conf, priors, targets);
    k_postA<<<BN * 4, 512>>>(conf, loc, priors, targets);
    k_topk<<<BN, TPK>>>(out);
}

// round 8
// speedup vs baseline: 1.5585x; 1.5585x over previous
#include <cuda_runtime.h>
#include <cstdint>

#define BN 64
#define PP 8732
#define CC 81
#define KT 16
#define NR (BN * PP)          // 558848
#define TR 96                 // rows per CE tile
#define CEB 5822              // ceil(NR/96): 5821 full + 1 tile of 32 rows
#define NCH 16
#define CHUNK 546
#define MBLK (BN * NCH)       // 1024 matchA blocks (first in grid)
#define THRESH 0.5f
#define VAR0 0.1f
#define VAR1 0.2f
#define TPK 1024
#define PPADK 9216            // 1024*9 uniform bound

// ---------------- scratch ----------------
__device__ __align__(16) float g_bto[NR];
__device__ __align__(16) int   g_bti[NR];
__device__ __align__(16) float g_lse[NR];
__device__ __align__(16) float g_lm[NR];
__device__ unsigned long long g_best[BN * KT];  // idempotent atomicMax accumulator
__device__ float g_loss_l[BN];
__device__ float g_loss_c[BN];
__device__ int   g_num_pos[BN];
__device__ int   g_done;                         // self-resetting

// ---------------- helpers ----------------
static __device__ __forceinline__ unsigned su32(const void* p) {
    return (unsigned)__cvta_generic_to_shared(p);
}
static __device__ __forceinline__ void cp16(unsigned sdst, const void* gsrc) {
    asm volatile("cp.async.cg.shared.global [%0], [%1], 16;" :: "r"(sdst), "l"(gsrc));
}
static __device__ __forceinline__ void cp_wait_all() {
    asm volatile("cp.async.wait_all;" ::: "memory");
}

// ---------------- kernel 1: matchA (blocks 0..MBLK-1) + CE (rest) ----------------
__global__ __launch_bounds__(128) void k_big(const float* __restrict__ conf,
                                             const float* __restrict__ priors,
                                             const float* __restrict__ targets) {
    __shared__ __align__(16) float s_buf[TR * CC];   // 31104 B, dual-purpose
    const int blk = blockIdx.x;
    const int tid = threadIdx.x;

    if (blk >= MBLK) {
        // ------- CE role: cp.async-staged tile, thread-per-row -------
        const int tile = blk - MBLK;
        const int row0 = tile * TR;
        const int nrows = (row0 + TR <= NR) ? TR : (NR - row0);
        const int nchunk = nrows * CC / 4;            // rows%4==0 in both cases
        const float* gsrc = conf + (size_t)row0 * CC;
        const unsigned sb = su32(s_buf);

        for (int i = tid; i < nchunk; i += 128)
            cp16(sb + i * 16, gsrc + i * 4);
        cp_wait_all();
        __syncthreads();

        if (tid < nrows) {
            const float* row = s_buf + tid * CC;
            float s0 = 0.0f, s1 = 0.0f, s2 = 0.0f, s3 = 0.0f;
#pragma unroll 10
            for (int i = 0; i + 3 < CC; i += 4) {
                s0 += __expf(row[i]);
                s1 += __expf(row[i + 1]);
                s2 += __expf(row[i + 2]);
                s3 += __expf(row[i + 3]);
            }
            s0 += __expf(row[CC - 1]);
            const float lse = __logf((s0 + s1) + (s2 + s3));
            g_lse[row0 + tid] = lse;
            g_lm[row0 + tid] = lse - row[0];
        }
    } else {
        // ------- matchA role -------
        float4* s_pr = (float4*)s_buf;                         // 546 * 16B
        float4* s_tt = (float4*)(s_buf + 2184);
        float*  s_area = s_buf + 2248;
        unsigned long long* s_best = (unsigned long long*)(s_buf + 2264);

        const int b = blk >> 4;
        const int c = blk & 15;

        if (tid < KT) {
            const float* tg = targets + (size_t)(b * KT + tid) * 6;
            s_tt[tid] = make_float4(tg[2], tg[3], tg[4], tg[5]);
            s_area[tid] = (tg[4] - tg[2]) * (tg[5] - tg[3]);
            s_best[tid] = 0ull;
        }
        const int p0 = c * CHUNK;
        const int np = (p0 + CHUNK <= PP) ? CHUNK : (PP - p0);
        for (int i = tid; i < np; i += 128)
            s_pr[i] = ((const float4*)priors)[p0 + i];
        __syncthreads();

        // per-prior best truth (first-max over k)
        for (int i = tid; i < np; i += 128) {
            const float4 pr = s_pr[i];
            const float parea = (pr.z - pr.x) * (pr.w - pr.y);
            float bestov = -1.0f;
            int besti = 0;
#pragma unroll
            for (int k = 0; k < KT; k++) {
                const float4 t = s_tt[k];
                float ix = fminf(t.z, pr.z) - fmaxf(t.x, pr.x);
                float iy = fminf(t.w, pr.w) - fmaxf(t.y, pr.y);
                float inter = fmaxf(ix, 0.0f) * fmaxf(iy, 0.0f);
                float ov = inter / (s_area[k] + parea - inter);
                if (ov > bestov) { bestov = ov; besti = k; }
            }
            g_bto[b * PP + p0 + i] = bestov;
            g_bti[b * PP + p0 + i] = besti;
        }

        // per-truth best prior: register + warp reduce, 1 atomic/warp/truth
        for (int k = 0; k < KT; k++) {
            const float4 t = s_tt[k];
            const float ta = s_area[k];
            unsigned long long key = 0ull;
            for (int i = tid; i < np; i += 128) {
                const float4 pr = s_pr[i];
                const float parea = (pr.z - pr.x) * (pr.w - pr.y);
                float ix = fminf(t.z, pr.z) - fmaxf(t.x, pr.x);
                float iy = fminf(t.w, pr.w) - fmaxf(t.y, pr.y);
                float inter = fmaxf(ix, 0.0f) * fmaxf(iy, 0.0f);
                float ov = inter / (ta + parea - inter);
                unsigned long long kk =
                    ((unsigned long long)__float_as_uint(ov) << 32) |
                    (unsigned long long)(0xFFFFFFFFu - (unsigned)(p0 + i));
                if (kk > key) key = kk;
            }
#pragma unroll
            for (int o = 16; o; o >>= 1) {
                unsigned long long other = __shfl_xor_sync(0xFFFFFFFFu, key, o);
                if (other > key) key = other;
            }
            if ((tid & 31) == 0)
                atomicMax(&s_best[k], key);
        }
        __syncthreads();
        if (tid < KT)
            atomicMax(&g_best[b * KT + tid], s_best[tid]);
    }
}

// ---------------- kernel 2: fused post (conf_t + L1 + pos-CE + radix topk + finalize) ----------------
__global__ __launch_bounds__(TPK) void k_post(const float* __restrict__ conf,
                                              const float* __restrict__ loc,
                                              const float* __restrict__ priors,
                                              const float* __restrict__ targets,
                                              float* __restrict__ out) {
    const int b = blockIdx.x;
    const int tid = threadIdx.x;
    const int lane = tid & 31;
    const int w = tid >> 5;
    const int bPP = b * PP;

    __shared__ __align__(16) float s_lm[PP];      // 34928 B
    __shared__ int s_hist[8][256];                // 8 copies vs atomic serialization
    __shared__ int s_cum[257];
    __shared__ int s_wtot[8], s_wsuf[8];
    __shared__ float4 s_tt[KT];
    __shared__ int s_lab[KT];
    __shared__ int s_fp[KT];
    __shared__ float s_fov[KT];
    __shared__ unsigned s_prefix;
    __shared__ int s_rem;
    __shared__ float s_rf[32], s_rs[32];
    __shared__ int s_ri[32];
    __shared__ float s_spos_sh, s_lsum_sh;
    __shared__ int s_npos_sh, s_last;

    if (tid < KT) {
        const float* tg = targets + (size_t)(b * KT + tid) * 6;
        s_lab[tid] = (int)tg[1];
        s_tt[tid] = make_float4(tg[2], tg[3], tg[4], tg[5]);
        unsigned long long key = g_best[b * KT + tid];
        s_fp[tid] = (int)(0xFFFFFFFFu - (unsigned)(key & 0xFFFFFFFFull));
        s_fov[tid] = __uint_as_float((unsigned)(key >> 32));
    }
    // FIX: zero ALL 2048 ints of the 8 histogram copies (TPK=1024 threads)
    for (int i = tid; i < 2048; i += TPK)
        ((int*)s_hist)[i] = 0;
    __syncthreads();

    // phase 1: build loss_mine in smem + positives accounting
    float lsum = 0.0f, spos = 0.0f;
    int cnt = 0;
    for (int p = tid; p < PP; p += TPK) {
        float ov = g_bto[bPP + p];
        int ki = g_bti[bPP + p];
#pragma unroll
        for (int k = 0; k < KT; k++)          // functional force-assign, last k wins
            if (p == s_fp[k]) { ov = s_fov[k]; ki = k; }
        const int ct = (ov < THRESH) ? 0 : s_lab[ki];
        float lmv = g_lm[bPP + p];
        if (ct > 0) {
            lmv = 0.0f;
            cnt++;
            spos += g_lse[bPP + p] - conf[(size_t)(bPP + p) * CC + ct];
            const float4 pr = ((const float4*)priors)[p];
            const float pcx = 0.5f * (pr.x + pr.z), pcy = 0.5f * (pr.y + pr.w);
            const float pw = pr.z - pr.x, ph = pr.w - pr.y;
            const float4 t = s_tt[ki];
            float g0 = (0.5f * (t.x + t.z) - pcx) / (VAR0 * pw);
            float g1 = (0.5f * (t.y + t.w) - pcy) / (VAR0 * ph);
            float g2 = logf((t.z - t.x) / pw) / VAR1;
            float g3 = logf((t.w - t.y) / ph) / VAR1;
            const float4 ld = ((const float4*)loc)[bPP + p];
            float d, ad;
            d = ld.x - g0; ad = fabsf(d); lsum += (ad < 1.0f) ? 0.5f * d * d : ad - 0.5f;
            d = ld.y - g1; ad = fabsf(d); lsum += (ad < 1.0f) ? 0.5f * d * d : ad - 0.5f;
            d = ld.z - g2; ad = fabsf(d); lsum += (ad < 1.0f) ? 0.5f * d * d : ad - 0.5f;
            d = ld.w - g3; ad = fabsf(d); lsum += (ad < 1.0f) ? 0.5f * d * d : ad - 0.5f;
        }
        s_lm[p] = lmv;
    }
#pragma unroll
    for (int o = 16; o; o >>= 1) {
        lsum += __shfl_xor_sync(0xFFFFFFFFu, lsum, o);
        spos += __shfl_xor_sync(0xFFFFFFFFu, spos, o);
        cnt  += __shfl_xor_sync(0xFFFFFFFFu, cnt, o);
    }
    if (lane == 0) { s_rf[w] = lsum; s_rs[w] = spos; s_ri[w] = cnt; }
    __syncthreads();
    if (tid < 32) {
        float L = s_rf[tid], S = s_rs[tid];
        int C = s_ri[tid];
#pragma unroll
        for (int o = 16; o; o >>= 1) {
            L += __shfl_xor_sync(0xFFFFFFFFu, L, o);
            S += __shfl_xor_sync(0xFFFFFFFFu, S, o);
            C += __shfl_xor_sync(0xFFFFFFFFu, C, o);
        }
        if (tid == 0) { s_lsum_sh = L; s_spos_sh = S; s_npos_sh = C; }
    }
    __syncthreads();

    const int npos = s_npos_sh;
    int k = 3 * npos;
    if (k > PP - 1) k = PP - 1;

    float T = 0.0f;
    if (k > 0) {
        if (tid == 0) { s_prefix = 0u; s_rem = k; }
        __syncthreads();
        for (int shift = 24; shift >= 0; shift -= 8) {
            const unsigned pref = s_prefix;
            const int rem = s_rem;
            const unsigned hm = (shift == 24) ? 0u : (0xFFFFFFFFu << (shift + 8));
            int* hist = s_hist[w & 7];
            for (int p = tid; p < PPADK; p += TPK) {
                const bool v = p < PP;
                const unsigned bits = v ? __float_as_uint(s_lm[p]) : 0u;
                const int bin = (bits >> shift) & 255;
                const bool pred = v && ((bits & hm) == pref);
                unsigned m = __match_any_sync(0xFFFFFFFFu, bin) &
                             __ballot_sync(0xFFFFFFFFu, pred);
                if (pred && lane == (__ffs(m) - 1))
                    atomicAdd(&hist[bin], __popc(m));
            }
            __syncthreads();
            int v = 0;
            if (tid < 256) {
                v = s_hist[0][tid] + s_hist[1][tid] + s_hist[2][tid] + s_hist[3][tid]
                  + s_hist[4][tid] + s_hist[5][tid] + s_hist[6][tid] + s_hist[7][tid];
                int sv = v;
#pragma unroll
                for (int o = 1; o < 32; o <<= 1) {      // warp suffix scan
                    int t2 = __shfl_down_sync(0xFFFFFFFFu, sv, o);
                    if (lane + o < 32) sv += t2;
                }
                if (lane == 0) s_wtot[w] = sv;
                s_cum[tid] = sv;                         // partial, fix after
            }
            __syncthreads();
            if (tid < 8) {
                int t2 = s_wtot[tid];
#pragma unroll
                for (int o = 1; o < 8; o <<= 1) {
                    int u = __shfl_down_sync(0xFFu, t2, o);
                    if (tid + o < 8) t2 += u;
                }
                s_wsuf[tid] = t2 - s_wtot[tid];
            }
            __syncthreads();
            if (tid < 256) {
                s_cum[tid] += s_wsuf[w];
                if (tid == 0) s_cum[256] = 0;
            }
            __syncthreads();
            if (tid < 256) {
                const int above = s_cum[tid + 1];
                if (s_cum[tid] >= rem && above < rem) {
                    s_prefix = pref | ((unsigned)tid << shift);
                    s_rem = rem - above;
                }
                // re-zero all 8 copies for this bin
#pragma unroll
                for (int cpy = 0; cpy < 8; cpy++) s_hist[cpy][tid] = 0;
            }
            __syncthreads();
        }
        const unsigned t = s_prefix;
        float sumgt = 0.0f;
        int cntgt = 0;
        for (int p = tid; p < PP; p += TPK) {
            const float lm = s_lm[p];
            if (__float_as_uint(lm) > t) { sumgt += lm; cntgt++; }
        }
#pragma unroll
        for (int o = 16; o; o >>= 1) {
            sumgt += __shfl_xor_sync(0xFFFFFFFFu, sumgt, o);
            cntgt += __shfl_xor_sync(0xFFFFFFFFu, cntgt, o);
        }
        if (lane == 0) { s_rf[w] = sumgt; s_ri[w] = cntgt; }
        __syncthreads();
        if (tid == 0) {
            float S = 0.0f; int C = 0;
            for (int i = 0; i < 32; i++) { S += s_rf[i]; C += s_ri[i]; }
            T = S + (float)(k - C) * __uint_as_float(t);
        }
    }

    if (tid == 0) {
        g_loss_l[b] = s_lsum_sh;
        g_loss_c[b] = s_spos_sh + T;
        g_num_pos[b] = npos;
        __threadfence();
        s_last = (atomicAdd(&g_done, 1) == BN - 1) ? 1 : 0;
    }
    __syncthreads();
    if (s_last) {
        if (tid < 64) {
            float lv = __ldcg(&g_loss_l[tid]);
            float cv = __ldcg(&g_loss_c[tid]);
            float nv = (float)__ldcg(&g_num_pos[tid]);
#pragma unroll
            for (int o = 16; o; o >>= 1) {
                lv += __shfl_xor_sync(0xFFFFFFFFu, lv, o);
                cv += __shfl_xor_sync(0xFFFFFFFFu, cv, o);
                nv += __shfl_xor_sync(0xFFFFFFFFu, nv, o);
            }
            if (lane == 0) { s_rf[w] = lv; s_rf[w + 2] = cv; s_rf[w + 4] = nv; }
        }
        __syncthreads();
        if (tid == 0) {
            const float n = fmaxf(s_rf[4] + s_rf[5], 1.0f);
            out[0] = (s_rf[0] + s_rf[1]) / n;
            out[1] = (s_rf[2] + s_rf[3]) / n;
            g_done = 0;   // self-reset for next replay
        }
    }
}

extern "C" void kernel_launch(void* const* d_in, const int* in_sizes, int n_in,
                              void* d_out, int out_size) {
    const float* loc = (const float*)d_in[0];
    const float* conf = (const float*)d_in[1];
    const float* priors = (const float*)d_in[2];
    const float* targets = (const float*)d_in[3];
    float* out = (float*)d_out;

    k_big<<<MBLK + CEB, 128>>>(conf, priors, targets);
    k_post<<<BN, TPK>>>(conf, loc, priors, targets, out);
}